// round 10
// baseline (speedup 1.0000x reference)
#include <cuda_runtime.h>
#include <cuda_bf16.h>

#define BB 256
#define TT 64
#define DD 2048
#define THRESHOLD 0.99f
#define EPSILON 0.01f
#define FULLM 0xffffffffu

// Grid: BB blocks (one per batch), 512 threads; thread owns one float4 of D.
// COMMON PATH (hs <= 3, ~96%): per-thread scalar weights from broadcast loads,
// no shuffles/smem/bar. RARE PATH (block-uniform): rows 4..7 issued BEFORE the
// warp-0 scan so the second DRAM round-trip overlaps it.
__global__ void __launch_bounds__(512) act_halting_kernel(
    const float* __restrict__ halt_probs,   // [B, T]
    const float* __restrict__ outputs,      // [B, T, D]
    const float* __restrict__ step_weights, // [B, T]
    float* __restrict__ out)                // [B*D] ++ [B] ++ [B*T]
{
    const int b    = blockIdx.x;
    const int tid  = threadIdx.x;
    const int lane = tid & 31;
    const int warp = tid >> 5;

    __shared__ float swsh[TT];
    __shared__ int   s_hs;

    const float* hpb = halt_probs   + b * TT;
    const float* swb = step_weights + b * TT;

    // ---- 1) Warp 0 pre-issues its full-row scan inputs (used only in the
    //         rare path, but issuing now means the scan never waits). ----
    float p_lo = 0.f, p_hi = 0.f, sw_lo = 0.f, sw_hi = 0.f;
    if (tid < 32) {
        p_lo  = hpb[lane];
        p_hi  = hpb[32 + lane];
        sw_lo = swb[lane];
        sw_hi = swb[32 + lane];
    }

    // ---- 2) Broadcast loads for the common path: hp[0..3], sw[0..3]. ----
    float4 hp4 = *reinterpret_cast<const float4*>(hpb);
    float4 st4 = *reinterpret_cast<const float4*>(swb);

    // ---- 3) Speculative row loads t=0..3 (always needed rows). ----
    const float4* base = reinterpret_cast<const float4*>(outputs)
                       + (size_t)b * TT * (DD / 4) + tid;
    float4 v0 = base[0 * (DD / 4)];
    float4 v1 = base[1 * (DD / 4)];
    float4 v2 = base[2 * (DD / 4)];
    float4 v3 = base[3 * (DD / 4)];

    // ---- 4) Sequential 4-step cumsum (bitwise-matches the reference). ----
    float c0 = hp4.x;
    float c1 = c0 + hp4.y;
    float c2 = c1 + hp4.z;
    float c3 = c2 + hp4.w;

    if (c3 >= THRESHOLD) {
        // ======== COMMON PATH: hs <= 3, per-thread scalar weights. ========
        float w0 = 0.f, w1 = 0.f, w2 = 0.f, w3 = 0.f;
        if (c0 >= THRESHOLD) {
            w0 = 1.0f * st4.x;                    // hs=0: remaining = 1
        } else if (c1 >= THRESHOLD) {
            w0 = hp4.x * st4.x;                   // hs=1: remaining = 1 - c0
            w1 = (1.0f - c0) * st4.y;
        } else if (c2 >= THRESHOLD) {
            w0 = hp4.x * st4.x;                   // hs=2: remaining = 1 - c1
            w1 = hp4.y * st4.y;
            w2 = (1.0f - c1) * st4.z;
        } else {
            w0 = hp4.x * st4.x;                   // hs=3: remaining = 1 - c2
            w1 = hp4.y * st4.y;
            w2 = hp4.z * st4.z;
            w3 = (1.0f - c2) * st4.w;
        }
        float S   = ((w0 + w1) + w2) + w3;
        float inv = 1.0f / fmaxf(S, EPSILON);
        w0 *= inv; w1 *= inv; w2 *= inv; w3 *= inv;

        float4 acc;
        acc.x = w0 * v0.x + w1 * v1.x + w2 * v2.x + w3 * v3.x;
        acc.y = w0 * v0.y + w1 * v1.y + w2 * v2.y + w3 * v3.y;
        acc.z = w0 * v0.z + w1 * v1.z + w2 * v2.z + w3 * v3.z;
        acc.w = w0 * v0.w + w1 * v1.w + w2 * v2.w + w3 * v3.w;
        reinterpret_cast<float4*>(out)[(size_t)b * (DD / 4) + tid] = acc;

        if (warp == 0) {
            float wl = (lane == 0) ? w0 : (lane == 1) ? w1
                     : (lane == 2) ? w2 : (lane == 3) ? w3 : 0.0f;
            out[BB * DD + BB + b * TT + lane]      = wl;
            out[BB * DD + BB + b * TT + 32 + lane] = 0.0f;
            if (lane == 0)
                out[BB * DD + b] = w0 * 1.0f + w1 * 2.0f + w2 * 3.0f + w3 * 4.0f;
        }
        return;
    }

    // ======== RARE PATH (block-uniform; hs >= 4 guaranteed). ========
    // Issue rows 4..7 NOW, before the scan: second round-trip overlaps it.
    // Weights beyond hs are exactly 0, so unpredicated loads are safe.
    float4 v4 = base[4 * (DD / 4)];
    float4 v5 = base[5 * (DD / 4)];
    float4 v6 = base[6 * (DD / 4)];
    float4 v7 = base[7 * (DD / 4)];

    if (tid < 32) {
        float c_lo = p_lo, c_hi = p_hi;
        #pragma unroll
        for (int o = 1; o < 32; o <<= 1) {
            float u = __shfl_up_sync(FULLM, c_lo, o);
            float v = __shfl_up_sync(FULLM, c_hi, o);
            if (lane >= o) { c_lo += u; c_hi += v; }
        }
        float tot_lo = __shfl_sync(FULLM, c_lo, 31);
        c_hi += tot_lo;

        unsigned bl = __ballot_sync(FULLM, c_lo >= THRESHOLD);
        unsigned bh = __ballot_sync(FULLM, c_hi >= THRESHOLD);
        int hs;
        if (bl)      hs = __ffs(bl) - 1;
        else if (bh) hs = 32 + __ffs(bh) - 1;
        else         hs = TT - 1;

        const int src = hs & 31;
        float cum_lo_at = __shfl_sync(FULLM, c_lo, src);
        float cum_hi_at = __shfl_sync(FULLM, c_hi, src);
        float p_lo_at   = __shfl_sync(FULLM, p_lo, src);
        float p_hi_at   = __shfl_sync(FULLM, p_hi, src);
        float cum_at = (hs < 32) ? cum_lo_at : cum_hi_at;
        float p_at   = (hs < 32) ? p_lo_at   : p_hi_at;
        float remaining = 1.0f - cum_at + p_at;

        const int t_lo = lane, t_hi = lane + 32;
        float w0 = (t_lo < hs) ? p_lo : ((t_lo == hs) ? remaining : 0.0f);
        float w1 = (t_hi < hs) ? p_hi : ((t_hi == hs) ? remaining : 0.0f);
        w0 *= sw_lo;
        w1 *= sw_hi;

        float s = w0 + w1;
        #pragma unroll
        for (int o = 16; o; o >>= 1) s += __shfl_xor_sync(FULLM, s, o);
        float inv = 1.0f / fmaxf(s, EPSILON);
        w0 *= inv;
        w1 *= inv;

        swsh[lane]      = w0;
        swsh[lane + 32] = w1;
        if (lane == 0) s_hs = hs;

        float pd = w0 * (float)(t_lo + 1) + w1 * (float)(t_hi + 1);
        #pragma unroll
        for (int o = 16; o; o >>= 1) pd += __shfl_xor_sync(FULLM, pd, o);
        if (lane == 0) out[BB * DD + b] = pd;
        out[BB * DD + BB + b * TT + lane]      = w0;
        out[BB * DD + BB + b * TT + 32 + lane] = w1;
    }
    __syncthreads();

    const int hs = s_hs;

    float4 acc;
    {
        float w0 = swsh[0], w1 = swsh[1], w2 = swsh[2], w3 = swsh[3];
        float w4 = swsh[4], w5 = swsh[5], w6 = swsh[6], w7 = swsh[7];
        acc.x = w0 * v0.x + w1 * v1.x + w2 * v2.x + w3 * v3.x
              + w4 * v4.x + w5 * v5.x + w6 * v6.x + w7 * v7.x;
        acc.y = w0 * v0.y + w1 * v1.y + w2 * v2.y + w3 * v3.y
              + w4 * v4.y + w5 * v5.y + w6 * v6.y + w7 * v7.y;
        acc.z = w0 * v0.z + w1 * v1.z + w2 * v2.z + w3 * v3.z
              + w4 * v4.z + w5 * v5.z + w6 * v6.z + w7 * v7.z;
        acc.w = w0 * v0.w + w1 * v1.w + w2 * v2.w + w3 * v3.w
              + w4 * v4.w + w5 * v5.w + w6 * v6.w + w7 * v7.w;
    }

    // Astronomically rare (P ~ 2e-6 per batch): hs >= 8.
    for (int t = 8; t <= hs; ++t) {
        float  w = swsh[t];
        float4 v = base[(size_t)t * (DD / 4)];
        acc.x = fmaf(w, v.x, acc.x);
        acc.y = fmaf(w, v.y, acc.y);
        acc.z = fmaf(w, v.z, acc.z);
        acc.w = fmaf(w, v.w, acc.w);
    }

    reinterpret_cast<float4*>(out)[(size_t)b * (DD / 4) + tid] = acc;
}

extern "C" void kernel_launch(void* const* d_in, const int* in_sizes, int n_in,
                              void* d_out, int out_size) {
    const float* halt_probs   = (const float*)d_in[0]; // [B,T,1] = 16384
    const float* outputs      = (const float*)d_in[1]; // [B,T,D] = 33554432
    const float* step_weights = (const float*)d_in[2]; // [B,T]   = 16384
    float* out = (float*)d_out;

    act_halting_kernel<<<BB, 512>>>(halt_probs, outputs, step_weights, out);
}

// round 11
// speedup vs baseline: 1.0048x; 1.0048x over previous
#include <cuda_runtime.h>
#include <cuda_bf16.h>

#define BB 256
#define TT 64
#define DD 2048
#define THRESHOLD 0.99f
#define EPSILON 0.01f
#define FULLM 0xffffffffu

// Grid: 128 CTAs (one per SM, single balanced wave), 512 threads.
// Each CTA handles TWO batches (2*bid, 2*bid+1); each thread owns one float4
// slice of D for both -> 8 independent speculative loads in flight (MLP 8).
// Weights: per-thread scalar computation (hs<=3 common path, ~96%/batch);
// rare batches fall back to a warp scan (warp 0 -> batch A, warp 1 -> batch B).
__global__ void __launch_bounds__(512) act_halting_kernel(
    const float* __restrict__ halt_probs,   // [B, T]
    const float* __restrict__ outputs,      // [B, T, D]
    const float* __restrict__ step_weights, // [B, T]
    float* __restrict__ out)                // [B*D] ++ [B] ++ [B*T]
{
    const int bid  = blockIdx.x;
    const int b0   = 2 * bid;
    const int b1   = b0 + 1;
    const int tid  = threadIdx.x;
    const int lane = tid & 31;
    const int warp = tid >> 5;

    __shared__ float swsh[2][TT];
    __shared__ int   s_hs[2];

    const float* hpb0 = halt_probs   + b0 * TT;
    const float* swb0 = step_weights + b0 * TT;
    const float* hpb1 = halt_probs   + b1 * TT;
    const float* swb1 = step_weights + b1 * TT;

    // ---- 1) Tiny broadcast loads first. ----
    float4 hp4a = *reinterpret_cast<const float4*>(hpb0);
    float4 st4a = *reinterpret_cast<const float4*>(swb0);
    float4 hp4b = *reinterpret_cast<const float4*>(hpb1);
    float4 st4b = *reinterpret_cast<const float4*>(swb1);

    // ---- 2) 8 speculative row loads (t=0..3 for both batches). ----
    const float4* baseA = reinterpret_cast<const float4*>(outputs)
                        + (size_t)b0 * TT * (DD / 4) + tid;
    const float4* baseB = reinterpret_cast<const float4*>(outputs)
                        + (size_t)b1 * TT * (DD / 4) + tid;
    float4 a0 = baseA[0 * (DD / 4)];
    float4 a1 = baseA[1 * (DD / 4)];
    float4 a2 = baseA[2 * (DD / 4)];
    float4 a3 = baseA[3 * (DD / 4)];
    float4 e0 = baseB[0 * (DD / 4)];
    float4 e1 = baseB[1 * (DD / 4)];
    float4 e2 = baseB[2 * (DD / 4)];
    float4 e3 = baseB[3 * (DD / 4)];

    // ---- 3) Scalar 4-step cumsum for both batches (matches reference). ----
    float ca0 = hp4a.x, ca1 = ca0 + hp4a.y, ca2 = ca1 + hp4a.z, ca3 = ca2 + hp4a.w;
    float cb0 = hp4b.x, cb1 = cb0 + hp4b.y, cb2 = cb1 + hp4b.z, cb3 = cb2 + hp4b.w;

    const bool rareA = !(ca3 >= THRESHOLD);   // block-uniform
    const bool rareB = !(cb3 >= THRESHOLD);   // block-uniform

    // Scalar weights for the common case, batch A.
    float wa0 = 0.f, wa1 = 0.f, wa2 = 0.f, wa3 = 0.f;
    if (!rareA) {
        if (ca0 >= THRESHOLD) {
            wa0 = 1.0f * st4a.x;
        } else if (ca1 >= THRESHOLD) {
            wa0 = hp4a.x * st4a.x; wa1 = (1.0f - ca0) * st4a.y;
        } else if (ca2 >= THRESHOLD) {
            wa0 = hp4a.x * st4a.x; wa1 = hp4a.y * st4a.y; wa2 = (1.0f - ca1) * st4a.z;
        } else {
            wa0 = hp4a.x * st4a.x; wa1 = hp4a.y * st4a.y;
            wa2 = hp4a.z * st4a.z; wa3 = (1.0f - ca2) * st4a.w;
        }
        float S = ((wa0 + wa1) + wa2) + wa3;
        float inv = 1.0f / fmaxf(S, EPSILON);
        wa0 *= inv; wa1 *= inv; wa2 *= inv; wa3 *= inv;
    }
    // Scalar weights for the common case, batch B.
    float wb0 = 0.f, wb1 = 0.f, wb2 = 0.f, wb3 = 0.f;
    if (!rareB) {
        if (cb0 >= THRESHOLD) {
            wb0 = 1.0f * st4b.x;
        } else if (cb1 >= THRESHOLD) {
            wb0 = hp4b.x * st4b.x; wb1 = (1.0f - cb0) * st4b.y;
        } else if (cb2 >= THRESHOLD) {
            wb0 = hp4b.x * st4b.x; wb1 = hp4b.y * st4b.y; wb2 = (1.0f - cb1) * st4b.z;
        } else {
            wb0 = hp4b.x * st4b.x; wb1 = hp4b.y * st4b.y;
            wb2 = hp4b.z * st4b.z; wb3 = (1.0f - cb2) * st4b.w;
        }
        float S = ((wb0 + wb1) + wb2) + wb3;
        float inv = 1.0f / fmaxf(S, EPSILON);
        wb0 *= inv; wb1 *= inv; wb2 *= inv; wb3 *= inv;
    }

    // ---- 4) Rare fallback (block-uniform): warp 0 scans A, warp 1 scans B. ----
    if (rareA || rareB) {
        const bool mine = (warp == 0) ? rareA : (warp == 1) ? rareB : false;
        if (mine) {
            const int    bi  = warp;                       // 0 -> A, 1 -> B
            const float* hpb = (warp == 0) ? hpb0 : hpb1;
            const float* swb = (warp == 0) ? swb0 : swb1;
            const int    bb  = (warp == 0) ? b0 : b1;

            float p_lo  = hpb[lane];
            float p_hi  = hpb[32 + lane];
            float sw_lo = swb[lane];
            float sw_hi = swb[32 + lane];

            float c_lo = p_lo, c_hi = p_hi;
            #pragma unroll
            for (int o = 1; o < 32; o <<= 1) {
                float u = __shfl_up_sync(FULLM, c_lo, o);
                float v = __shfl_up_sync(FULLM, c_hi, o);
                if (lane >= o) { c_lo += u; c_hi += v; }
            }
            float tot_lo = __shfl_sync(FULLM, c_lo, 31);
            c_hi += tot_lo;

            unsigned bl = __ballot_sync(FULLM, c_lo >= THRESHOLD);
            unsigned bh = __ballot_sync(FULLM, c_hi >= THRESHOLD);
            int hs;
            if (bl)      hs = __ffs(bl) - 1;
            else if (bh) hs = 32 + __ffs(bh) - 1;
            else         hs = TT - 1;

            const int src = hs & 31;
            float cum_lo_at = __shfl_sync(FULLM, c_lo, src);
            float cum_hi_at = __shfl_sync(FULLM, c_hi, src);
            float p_lo_at   = __shfl_sync(FULLM, p_lo, src);
            float p_hi_at   = __shfl_sync(FULLM, p_hi, src);
            float cum_at = (hs < 32) ? cum_lo_at : cum_hi_at;
            float p_at   = (hs < 32) ? p_lo_at   : p_hi_at;
            float remaining = 1.0f - cum_at + p_at;

            const int t_lo = lane, t_hi = lane + 32;
            float w0 = (t_lo < hs) ? p_lo : ((t_lo == hs) ? remaining : 0.0f);
            float w1 = (t_hi < hs) ? p_hi : ((t_hi == hs) ? remaining : 0.0f);
            w0 *= sw_lo;
            w1 *= sw_hi;

            float s = w0 + w1;
            #pragma unroll
            for (int o = 16; o; o >>= 1) s += __shfl_xor_sync(FULLM, s, o);
            float inv = 1.0f / fmaxf(s, EPSILON);
            w0 *= inv;
            w1 *= inv;

            swsh[bi][lane]      = w0;
            swsh[bi][lane + 32] = w1;
            if (lane == 0) s_hs[bi] = hs;

            float pd = w0 * (float)(t_lo + 1) + w1 * (float)(t_hi + 1);
            #pragma unroll
            for (int o = 16; o; o >>= 1) pd += __shfl_xor_sync(FULLM, pd, o);
            if (lane == 0) out[BB * DD + bb] = pd;
            out[BB * DD + BB + bb * TT + lane]      = w0;
            out[BB * DD + BB + bb * TT + 32 + lane] = w1;
        }
        __syncthreads();
    }

    // ---- 5) Batch A accumulate + store. ----
    {
        float u0 = wa0, u1 = wa1, u2 = wa2, u3 = wa3;
        if (rareA) { u0 = swsh[0][0]; u1 = swsh[0][1]; u2 = swsh[0][2]; u3 = swsh[0][3]; }
        float4 acc;
        acc.x = u0 * a0.x + u1 * a1.x + u2 * a2.x + u3 * a3.x;
        acc.y = u0 * a0.y + u1 * a1.y + u2 * a2.y + u3 * a3.y;
        acc.z = u0 * a0.z + u1 * a1.z + u2 * a2.z + u3 * a3.z;
        acc.w = u0 * a0.w + u1 * a1.w + u2 * a2.w + u3 * a3.w;
        if (rareA) {
            const int hs = s_hs[0];
            float4 v4 = baseA[4 * (DD / 4)];
            float4 v5 = baseA[5 * (DD / 4)];
            float4 v6 = baseA[6 * (DD / 4)];
            float4 v7 = baseA[7 * (DD / 4)];
            float w4 = swsh[0][4], w5 = swsh[0][5], w6 = swsh[0][6], w7 = swsh[0][7];
            acc.x += w4 * v4.x + w5 * v5.x + w6 * v6.x + w7 * v7.x;
            acc.y += w4 * v4.y + w5 * v5.y + w6 * v6.y + w7 * v7.y;
            acc.z += w4 * v4.z + w5 * v5.z + w6 * v6.z + w7 * v7.z;
            acc.w += w4 * v4.w + w5 * v5.w + w6 * v6.w + w7 * v7.w;
            for (int t = 8; t <= hs; ++t) {
                float  w = swsh[0][t];
                float4 v = baseA[(size_t)t * (DD / 4)];
                acc.x = fmaf(w, v.x, acc.x);
                acc.y = fmaf(w, v.y, acc.y);
                acc.z = fmaf(w, v.z, acc.z);
                acc.w = fmaf(w, v.w, acc.w);
            }
        }
        reinterpret_cast<float4*>(out)[(size_t)b0 * (DD / 4) + tid] = acc;
    }

    // ---- 6) Batch B accumulate + store. ----
    {
        float u0 = wb0, u1 = wb1, u2 = wb2, u3 = wb3;
        if (rareB) { u0 = swsh[1][0]; u1 = swsh[1][1]; u2 = swsh[1][2]; u3 = swsh[1][3]; }
        float4 acc;
        acc.x = u0 * e0.x + u1 * e1.x + u2 * e2.x + u3 * e3.x;
        acc.y = u0 * e0.y + u1 * e1.y + u2 * e2.y + u3 * e3.y;
        acc.z = u0 * e0.z + u1 * e1.z + u2 * e2.z + u3 * e3.z;
        acc.w = u0 * e0.w + u1 * e1.w + u2 * e2.w + u3 * e3.w;
        if (rareB) {
            const int hs = s_hs[1];
            float4 v4 = baseB[4 * (DD / 4)];
            float4 v5 = baseB[5 * (DD / 4)];
            float4 v6 = baseB[6 * (DD / 4)];
            float4 v7 = baseB[7 * (DD / 4)];
            float w4 = swsh[1][4], w5 = swsh[1][5], w6 = swsh[1][6], w7 = swsh[1][7];
            acc.x += w4 * v4.x + w5 * v5.x + w6 * v6.x + w7 * v7.x;
            acc.y += w4 * v4.y + w5 * v5.y + w6 * v6.y + w7 * v7.y;
            acc.z += w4 * v4.z + w5 * v5.z + w6 * v6.z + w7 * v7.z;
            acc.w += w4 * v4.w + w5 * v5.w + w6 * v6.w + w7 * v7.w;
            for (int t = 8; t <= hs; ++t) {
                float  w = swsh[1][t];
                float4 v = baseB[(size_t)t * (DD / 4)];
                acc.x = fmaf(w, v.x, acc.x);
                acc.y = fmaf(w, v.y, acc.y);
                acc.z = fmaf(w, v.z, acc.z);
                acc.w = fmaf(w, v.w, acc.w);
            }
        }
        reinterpret_cast<float4*>(out)[(size_t)b1 * (DD / 4) + tid] = acc;
    }

    // ---- 7) Common-path side outputs: warp 0 -> batch A, warp 1 -> batch B. ----
    if (warp == 0 && !rareA) {
        float wl = (lane == 0) ? wa0 : (lane == 1) ? wa1
                 : (lane == 2) ? wa2 : (lane == 3) ? wa3 : 0.0f;
        out[BB * DD + BB + b0 * TT + lane]      = wl;
        out[BB * DD + BB + b0 * TT + 32 + lane] = 0.0f;
        if (lane == 0)
            out[BB * DD + b0] = wa0 * 1.0f + wa1 * 2.0f + wa2 * 3.0f + wa3 * 4.0f;
    }
    if (warp == 1 && !rareB) {
        float wl = (lane == 0) ? wb0 : (lane == 1) ? wb1
                 : (lane == 2) ? wb2 : (lane == 3) ? wb3 : 0.0f;
        out[BB * DD + BB + b1 * TT + lane]      = wl;
        out[BB * DD + BB + b1 * TT + 32 + lane] = 0.0f;
        if (lane == 0)
            out[BB * DD + b1] = wb0 * 1.0f + wb1 * 2.0f + wb2 * 3.0f + wb3 * 4.0f;
    }
}

extern "C" void kernel_launch(void* const* d_in, const int* in_sizes, int n_in,
                              void* d_out, int out_size) {
    const float* halt_probs   = (const float*)d_in[0]; // [B,T,1] = 16384
    const float* outputs      = (const float*)d_in[1]; // [B,T,D] = 33554432
    const float* step_weights = (const float*)d_in[2]; // [B,T]   = 16384
    float* out = (float*)d_out;

    act_halting_kernel<<<BB / 2, 512>>>(halt_probs, outputs, step_weights, out);
}